// round 14
// baseline (speedup 1.0000x reference)
#include <cuda_runtime.h>
#include <cstdint>

// ICGP_Convnp: out[b,m,k,c] = sum_n feat[b,n,k,c] * exp(-0.5*((xa[b,n,c]-xt[b,m,c])/std[k,c])^2)
// B=8, N1=N2=1024, D=1, K=5, C=3.
// lane -> 2 m's, warp -> n-chunk, k-loop = packed fma.rn.f32x2.
// 24 warps/CTA (reg cap 85 -> no spills) to raise issue-slot utilization.

constexpr int B_  = 8;
constexpr int N1_ = 1024;
constexpr int N2_ = 1024;

constexpr int WARPS    = 24;
constexpr int THREADS  = WARPS * 32;       // 768
constexpr int M_BLK    = 64;               // 2 m per lane
constexpr int FSTRIDE  = 16;               // feature row padded 15 -> 16 floats (64B)
constexpr int XSTRIDE  = 4;
constexpr int SMEM_FLOATS = N1_ * XSTRIDE + N1_ * FSTRIDE;  // 20480 floats = 80 KB
constexpr int HWARPS   = 12;               // two-stage reduction split
constexpr int RSTRIDE  = 17;               // padded reduction row (bank-conflict-free)

__device__ __forceinline__ float ex2f(float x) {
    float y;
    asm("ex2.approx.ftz.f32 %0, %1;" : "=f"(y) : "f"(x));
    return y;
}
__device__ __forceinline__ uint64_t packf2(float lo, float hi) {
    uint64_t r;
    asm("mov.b64 %0, {%1, %2};" : "=l"(r) : "f"(lo), "f"(hi));
    return r;
}
__device__ __forceinline__ uint64_t fma2(uint64_t a, uint64_t b, uint64_t c) {
    uint64_t d;
    asm("fma.rn.f32x2 %0, %1, %2, %3;" : "=l"(d) : "l"(a), "l"(b), "l"(c));
    return d;
}
__device__ __forceinline__ void unpackf2(uint64_t v, float& lo, float& hi) {
    asm("mov.b64 {%0, %1}, %2;" : "=f"(lo), "=f"(hi) : "l"(v));
}

__global__ __launch_bounds__(THREADS, 1)
void icgp_kernel(const float* __restrict__ xa, const float* __restrict__ feat,
                 const float* __restrict__ xt, const float* __restrict__ lstd,
                 float* __restrict__ out)
{
    extern __shared__ float smem[];
    float* s_xa = smem;                      // [N1][4]
    float* s_ft = smem + N1_ * XSTRIDE;      // [N1][16], slots 0..14 = (k,c), slot 15 = 0
    __shared__ float s_coef[16];
    __shared__ int   s_uni;

    const int b      = blockIdx.y;
    const int tid    = threadIdx.x;
    const int wid    = tid >> 5;
    const int lane   = tid & 31;
    const int m_base = blockIdx.x * M_BLK;
    const int m0     = m_base + lane;
    const int m1     = m0 + 32;

    // coef[k,c] = -0.5*log2(e) / (exp(log_std)+eps)^2 ; slot 15 = 0 (dummy, feature=0)
    if (tid < 15) {
        float s = __expf(lstd[tid]) + 1e-6f;
        s_coef[tid] = -0.72134752044448170f / (s * s);
    }
    if (tid == 15) s_coef[15] = 0.f;
    __syncthreads();
    if (tid == 0) {
        int u = 1;
        #pragma unroll
        for (int i = 1; i < 15; i++)
            u &= (__float_as_int(s_coef[i]) == __float_as_int(s_coef[0]));
        s_uni = u;
    }

    // Stage xa[b] into padded shared.
    const float* xa_b = xa + (size_t)b * N1_ * 3;
    for (int n = tid; n < N1_; n += THREADS) {
        s_xa[n * XSTRIDE + 0] = xa_b[n * 3 + 0];
        s_xa[n * XSTRIDE + 1] = xa_b[n * 3 + 1];
        s_xa[n * XSTRIDE + 2] = xa_b[n * 3 + 2];
        s_xa[n * XSTRIDE + 3] = 0.f;
    }
    // Zero slot 15 of every feature row.
    for (int n = tid; n < N1_; n += THREADS)
        s_ft[n * FSTRIDE + 15] = 0.f;
    // Stage features[b] with float4 loads (3840 float4, 16B-aligned).
    {
        const float4* f4 = reinterpret_cast<const float4*>(feat + (size_t)b * N1_ * 15);
        for (int v = tid; v < N1_ * 15 / 4; v += THREADS) {
            float4 f = f4[v];
            int g = v * 4;
            int n = g / 15, s = g - n * 15;
            s_ft[n * FSTRIDE + s] = f.x;
            if (++s == 15) { s = 0; n++; }
            s_ft[n * FSTRIDE + s] = f.y;
            if (++s == 15) { s = 0; n++; }
            s_ft[n * FSTRIDE + s] = f.z;
            if (++s == 15) { s = 0; n++; }
            s_ft[n * FSTRIDE + s] = f.w;
        }
    }
    __syncthreads();

    // Per-lane target points (2 m's).
    const float* xt_b = xt + (size_t)b * N2_ * 3;
    const float t0r = xt_b[m0 * 3 + 0], t1r = xt_b[m0 * 3 + 1], t2r = xt_b[m0 * 3 + 2];
    const float u0r = xt_b[m1 * 3 + 0], u1r = xt_b[m1 * 3 + 1], u2r = xt_b[m1 * 3 + 2];

    // Uneven n-chunks: first 16 warps take 43, last 8 take 42 (total 1024).
    const int nlen = 42 + (wid < 16 ? 1 : 0);
    const int n0   = wid * 42 + (wid < 16 ? wid : 16);

    uint64_t acc2[2][8];
    #pragma unroll
    for (int j = 0; j < 8; j++) { acc2[0][j] = 0ull; acc2[1][j] = 0ull; }

    if (s_uni) {
        // w_c = exp2(-((a_c - t_c)*sgm)^2),  sgm = sqrt(-c0)
        const float sgm = sqrtf(-s_coef[0]);
        const float t0 = t0r * sgm, t1 = t1r * sgm, t2 = t2r * sgm;
        const float v0 = u0r * sgm, v1 = u1r * sgm, v2 = u2r * sgm;
        for (int n = n0; n < n0 + nlen; n++) {
            float4 a = *reinterpret_cast<const float4*>(&s_xa[n * XSTRIDE]);   // broadcast
            float p0 = fmaf(a.x, sgm, -t0);
            float p1 = fmaf(a.y, sgm, -t1);
            float p2 = fmaf(a.z, sgm, -t2);
            float w0 = ex2f(p0 * -p0), w1 = ex2f(p1 * -p1), w2 = ex2f(p2 * -p2);
            float q0 = fmaf(a.x, sgm, -v0);
            float q1 = fmaf(a.y, sgm, -v1);
            float q2 = fmaf(a.z, sgm, -v2);
            float x0 = ex2f(q0 * -q0), x1 = ex2f(q1 * -q1), x2 = ex2f(q2 * -q2);
            // packed weight pattern over 16-slot row: A B C A B C A B
            uint64_t A0 = packf2(w0, w1), B0 = packf2(w2, w0), C0 = packf2(w1, w2);
            uint64_t A1 = packf2(x0, x1), B1 = packf2(x2, x0), C1 = packf2(x1, x2);
            const ulonglong2* fp = reinterpret_cast<const ulonglong2*>(&s_ft[n * FSTRIDE]);
            ulonglong2 pA = fp[0];
            acc2[0][0] = fma2(pA.x, A0, acc2[0][0]);
            acc2[1][0] = fma2(pA.x, A1, acc2[1][0]);
            acc2[0][1] = fma2(pA.y, B0, acc2[0][1]);
            acc2[1][1] = fma2(pA.y, B1, acc2[1][1]);
            ulonglong2 pB = fp[1];
            acc2[0][2] = fma2(pB.x, C0, acc2[0][2]);
            acc2[1][2] = fma2(pB.x, C1, acc2[1][2]);
            acc2[0][3] = fma2(pB.y, A0, acc2[0][3]);
            acc2[1][3] = fma2(pB.y, A1, acc2[1][3]);
            ulonglong2 pC = fp[2];
            acc2[0][4] = fma2(pC.x, B0, acc2[0][4]);
            acc2[1][4] = fma2(pC.x, B1, acc2[1][4]);
            acc2[0][5] = fma2(pC.y, C0, acc2[0][5]);
            acc2[1][5] = fma2(pC.y, C1, acc2[1][5]);
            ulonglong2 pD = fp[3];
            acc2[0][6] = fma2(pD.x, A0, acc2[0][6]);
            acc2[1][6] = fma2(pD.x, A1, acc2[1][6]);
            acc2[0][7] = fma2(pD.y, B0, acc2[0][7]);   // slot15 feature = 0
            acc2[1][7] = fma2(pD.y, B1, acc2[1][7]);
        }
    } else {
        // General path: per-(k,c) bandwidth; packed accumulation (same epilogue).
        float cf[16];
        #pragma unroll
        for (int i = 0; i < 16; i++) cf[i] = s_coef[i];
        for (int n = n0; n < n0 + nlen; n++) {
            float4 a = *reinterpret_cast<const float4*>(&s_xa[n * XSTRIDE]);
            float qd[3], qe[3];
            qd[0] = (a.x - t0r) * (a.x - t0r);
            qd[1] = (a.y - t1r) * (a.y - t1r);
            qd[2] = (a.z - t2r) * (a.z - t2r);
            qe[0] = (a.x - u0r) * (a.x - u0r);
            qe[1] = (a.y - u1r) * (a.y - u1r);
            qe[2] = (a.z - u2r) * (a.z - u2r);
            const ulonglong2* fp = reinterpret_cast<const ulonglong2*>(&s_ft[n * FSTRIDE]);
            #pragma unroll
            for (int j = 0; j < 8; j++) {
                const int s0 = 2 * j, s1 = 2 * j + 1;
                uint64_t fpair = (j & 1) ? fp[j >> 1].y : fp[j >> 1].x;
                uint64_t W0 = packf2(ex2f(qd[s0 % 3] * cf[s0]), ex2f(qd[s1 % 3] * cf[s1]));
                uint64_t W1 = packf2(ex2f(qe[s0 % 3] * cf[s0]), ex2f(qe[s1 % 3] * cf[s1]));
                acc2[0][j] = fma2(fpair, W0, acc2[0][j]);
                acc2[1][j] = fma2(fpair, W1, acc2[1][j]);
            }
        }
    }

    // Unpack to 15 scalars per m.
    float acc_s[2][15];
    #pragma unroll
    for (int t = 0; t < 2; t++) {
        #pragma unroll
        for (int j = 0; j < 8; j++) {
            float lo, hi;
            unpackf2(acc2[t][j], lo, hi);
            if (2*j     < 15) acc_s[t][2*j]     = lo;
            if (2*j + 1 < 15) acc_s[t][2*j + 1] = hi;
        }
    }

    // Two-stage cross-warp reduction over 24 warps, padded rows (RSTRIDE=17).
    __syncthreads();                          // everyone done reading s_xa / s_ft
    float* red = smem;                        // [12][64][17] = 13056 floats <= 20480
    if (wid >= HWARPS) {
        float* d0 = &red[((wid - HWARPS) * 64 + lane) * RSTRIDE];
        float* d1 = &red[((wid - HWARPS) * 64 + 32 + lane) * RSTRIDE];
        #pragma unroll
        for (int i = 0; i < 15; i++) { d0[i] = acc_s[0][i]; d1[i] = acc_s[1][i]; }
    }
    __syncthreads();
    if (wid < HWARPS) {
        float* d0 = &red[(wid * 64 + lane) * RSTRIDE];
        float* d1 = &red[(wid * 64 + 32 + lane) * RSTRIDE];
        #pragma unroll
        for (int i = 0; i < 15; i++) { d0[i] += acc_s[0][i]; d1[i] += acc_s[1][i]; }
    }
    __syncthreads();

    // 960 outputs per block; 768 threads -> strided loop.
    for (int o = tid; o < M_BLK * 15; o += THREADS) {
        int m_loc = o / 15, i = o - m_loc * 15;
        float s = 0.f;
        #pragma unroll
        for (int w = 0; w < HWARPS; w++)
            s += red[(w * 64 + m_loc) * RSTRIDE + i];
        out[((size_t)b * N2_ + m_base) * 15 + o] = s;
    }
}

extern "C" void kernel_launch(void* const* d_in, const int* in_sizes, int n_in,
                              void* d_out, int out_size)
{
    const float* xa   = (const float*)d_in[0];
    const float* feat = (const float*)d_in[1];
    const float* xt   = (const float*)d_in[2];
    const float* lstd = (const float*)d_in[3];
    float* out = (float*)d_out;

    const size_t smem = SMEM_FLOATS * sizeof(float);   // 80 KB dynamic
    cudaFuncSetAttribute(icgp_kernel, cudaFuncAttributeMaxDynamicSharedMemorySize, (int)smem);

    dim3 grid(N2_ / M_BLK, B_);   // (16, 8) = 128 blocks
    icgp_kernel<<<grid, THREADS, smem>>>(xa, feat, xt, lstd, out);
}

// round 15
// speedup vs baseline: 1.1052x; 1.1052x over previous
#include <cuda_runtime.h>
#include <cstdint>

// ICGP_Convnp: out[b,m,k,c] = sum_n feat[b,n,k,c] * exp(-0.5*((xa[b,n,c]-xt[b,m,c])/std[k,c])^2)
// B=8, N1=N2=1024, D=1, K=5, C=3.
// lane -> 2 m's, warp -> n-chunk (64), k-loop = packed fma.rn.f32x2.
// Software-pipelined main loop: prefetch next n's xa + feature row past the LDS latency.

constexpr int B_  = 8;
constexpr int N1_ = 1024;
constexpr int N2_ = 1024;

constexpr int WARPS    = 16;
constexpr int THREADS  = WARPS * 32;       // 512
constexpr int NCHUNK   = N1_ / WARPS;      // 64 n per warp
constexpr int M_BLK    = 64;               // 2 m per lane
constexpr int FSTRIDE  = 16;               // feature row padded 15 -> 16 floats (64B)
constexpr int XSTRIDE  = 4;
// + one pad feature row so the last prefetch (row 1024) stays in-bounds.
constexpr int SMEM_FLOATS = N1_ * XSTRIDE + (N1_ + 1) * FSTRIDE;  // 20496 floats
constexpr int RSTRIDE  = 17;               // padded reduction row (conflict-free)

__device__ __forceinline__ float ex2f(float x) {
    float y;
    asm("ex2.approx.ftz.f32 %0, %1;" : "=f"(y) : "f"(x));
    return y;
}
__device__ __forceinline__ uint64_t packf2(float lo, float hi) {
    uint64_t r;
    asm("mov.b64 %0, {%1, %2};" : "=l"(r) : "f"(lo), "f"(hi));
    return r;
}
__device__ __forceinline__ uint64_t fma2(uint64_t a, uint64_t b, uint64_t c) {
    uint64_t d;
    asm("fma.rn.f32x2 %0, %1, %2, %3;" : "=l"(d) : "l"(a), "l"(b), "l"(c));
    return d;
}
__device__ __forceinline__ void unpackf2(uint64_t v, float& lo, float& hi) {
    asm("mov.b64 {%0, %1}, %2;" : "=f"(lo), "=f"(hi) : "l"(v));
}

__global__ __launch_bounds__(THREADS, 1)
void icgp_kernel(const float* __restrict__ xa, const float* __restrict__ feat,
                 const float* __restrict__ xt, const float* __restrict__ lstd,
                 float* __restrict__ out)
{
    extern __shared__ float smem[];
    float* s_xa = smem;                      // [N1][4]
    float* s_ft = smem + N1_ * XSTRIDE;      // [N1+1][16], slots 0..14 = (k,c), slot 15 = 0
    __shared__ float s_coef[16];
    __shared__ int   s_uni;

    const int b      = blockIdx.y;
    const int tid    = threadIdx.x;
    const int wid    = tid >> 5;
    const int lane   = tid & 31;
    const int m_base = blockIdx.x * M_BLK;
    const int m0     = m_base + lane;
    const int m1     = m0 + 32;

    // coef[k,c] = -0.5*log2(e) / (exp(log_std)+eps)^2
    if (tid < 15) {
        float s = __expf(lstd[tid]) + 1e-6f;
        s_coef[tid] = -0.72134752044448170f / (s * s);
    }
    if (tid == 15) s_coef[15] = 0.f;
    __syncthreads();
    if (tid == 0) {
        int u = 1;
        #pragma unroll
        for (int i = 1; i < 15; i++)
            u &= (__float_as_int(s_coef[i]) == __float_as_int(s_coef[0]));
        s_uni = u;
    }

    // Stage xa[b] into padded shared.
    const float* xa_b = xa + (size_t)b * N1_ * 3;
    for (int n = tid; n < N1_; n += THREADS) {
        s_xa[n * XSTRIDE + 0] = xa_b[n * 3 + 0];
        s_xa[n * XSTRIDE + 1] = xa_b[n * 3 + 1];
        s_xa[n * XSTRIDE + 2] = xa_b[n * 3 + 2];
        s_xa[n * XSTRIDE + 3] = 0.f;
    }
    // Zero slot 15 of every feature row + the pad row (row N1).
    for (int n = tid; n < N1_; n += THREADS)
        s_ft[n * FSTRIDE + 15] = 0.f;
    if (tid < FSTRIDE) s_ft[N1_ * FSTRIDE + tid] = 0.f;
    // Stage features[b] with float4 loads (3840 float4, 16B-aligned).
    {
        const float4* f4 = reinterpret_cast<const float4*>(feat + (size_t)b * N1_ * 15);
        for (int v = tid; v < N1_ * 15 / 4; v += THREADS) {
            float4 f = f4[v];
            int g = v * 4;
            int n = g / 15, s = g - n * 15;
            s_ft[n * FSTRIDE + s] = f.x;
            if (++s == 15) { s = 0; n++; }
            s_ft[n * FSTRIDE + s] = f.y;
            if (++s == 15) { s = 0; n++; }
            s_ft[n * FSTRIDE + s] = f.z;
            if (++s == 15) { s = 0; n++; }
            s_ft[n * FSTRIDE + s] = f.w;
        }
    }
    __syncthreads();

    // Per-lane target points (2 m's).
    const float* xt_b = xt + (size_t)b * N2_ * 3;
    const float t0r = xt_b[m0 * 3 + 0], t1r = xt_b[m0 * 3 + 1], t2r = xt_b[m0 * 3 + 2];
    const float u0r = xt_b[m1 * 3 + 0], u1r = xt_b[m1 * 3 + 1], u2r = xt_b[m1 * 3 + 2];

    const int n0 = wid * NCHUNK;

    uint64_t acc2[2][8];
    #pragma unroll
    for (int j = 0; j < 8; j++) { acc2[0][j] = 0ull; acc2[1][j] = 0ull; }

    if (s_uni) {
        // w_c = exp2(-((a_c - t_c)*sgm)^2),  sgm = sqrt(-c0)
        const float sgm = sqrtf(-s_coef[0]);
        const float t0 = t0r * sgm, t1 = t1r * sgm, t2 = t2r * sgm;
        const float v0 = u0r * sgm, v1 = u1r * sgm, v2 = u2r * sgm;

        const float4*     xp = reinterpret_cast<const float4*>(&s_xa[n0 * XSTRIDE]);
        const ulonglong2* fp = reinterpret_cast<const ulonglong2*>(&s_ft[n0 * FSTRIDE]);

        // Pipeline prologue: load iteration 0's operands.
        float4 a_c = xp[0];
        ulonglong2 pA = fp[0], pB = fp[1], pC = fp[2], pD = fp[3];

        #pragma unroll 2
        for (int it = 0; it < NCHUNK; it++) {
            // Prefetch next iteration (pad row makes it always in-bounds).
            float4 a_n = xp[it + 1];
            ulonglong2 qA = fp[4*(it+1) + 0], qB = fp[4*(it+1) + 1],
                       qC = fp[4*(it+1) + 2], qD = fp[4*(it+1) + 3];

            float p0 = fmaf(a_c.x, sgm, -t0);
            float p1 = fmaf(a_c.y, sgm, -t1);
            float p2 = fmaf(a_c.z, sgm, -t2);
            float w0 = ex2f(p0 * -p0), w1 = ex2f(p1 * -p1), w2 = ex2f(p2 * -p2);
            float q0 = fmaf(a_c.x, sgm, -v0);
            float q1 = fmaf(a_c.y, sgm, -v1);
            float q2 = fmaf(a_c.z, sgm, -v2);
            float x0 = ex2f(q0 * -q0), x1 = ex2f(q1 * -q1), x2 = ex2f(q2 * -q2);
            // packed weight pattern over 16-slot row: A B C A B C A B
            uint64_t A0 = packf2(w0, w1), B0 = packf2(w2, w0), C0 = packf2(w1, w2);
            uint64_t A1 = packf2(x0, x1), B1 = packf2(x2, x0), C1 = packf2(x1, x2);

            acc2[0][0] = fma2(pA.x, A0, acc2[0][0]);
            acc2[1][0] = fma2(pA.x, A1, acc2[1][0]);
            acc2[0][1] = fma2(pA.y, B0, acc2[0][1]);
            acc2[1][1] = fma2(pA.y, B1, acc2[1][1]);
            acc2[0][2] = fma2(pB.x, C0, acc2[0][2]);
            acc2[1][2] = fma2(pB.x, C1, acc2[1][2]);
            acc2[0][3] = fma2(pB.y, A0, acc2[0][3]);
            acc2[1][3] = fma2(pB.y, A1, acc2[1][3]);
            acc2[0][4] = fma2(pC.x, B0, acc2[0][4]);
            acc2[1][4] = fma2(pC.x, B1, acc2[1][4]);
            acc2[0][5] = fma2(pC.y, C0, acc2[0][5]);
            acc2[1][5] = fma2(pC.y, C1, acc2[1][5]);
            acc2[0][6] = fma2(pD.x, A0, acc2[0][6]);
            acc2[1][6] = fma2(pD.x, A1, acc2[1][6]);
            acc2[0][7] = fma2(pD.y, B0, acc2[0][7]);   // slot15 feature = 0
            acc2[1][7] = fma2(pD.y, B1, acc2[1][7]);

            a_c = a_n; pA = qA; pB = qB; pC = qC; pD = qD;
        }
    } else {
        // General path: per-(k,c) bandwidth; packed accumulation (same epilogue).
        float cf[16];
        #pragma unroll
        for (int i = 0; i < 16; i++) cf[i] = s_coef[i];
        for (int n = n0; n < n0 + NCHUNK; n++) {
            float4 a = *reinterpret_cast<const float4*>(&s_xa[n * XSTRIDE]);
            float qd[3], qe[3];
            qd[0] = (a.x - t0r) * (a.x - t0r);
            qd[1] = (a.y - t1r) * (a.y - t1r);
            qd[2] = (a.z - t2r) * (a.z - t2r);
            qe[0] = (a.x - u0r) * (a.x - u0r);
            qe[1] = (a.y - u1r) * (a.y - u1r);
            qe[2] = (a.z - u2r) * (a.z - u2r);
            const ulonglong2* fp = reinterpret_cast<const ulonglong2*>(&s_ft[n * FSTRIDE]);
            #pragma unroll
            for (int j = 0; j < 8; j++) {
                const int s0 = 2 * j, s1 = 2 * j + 1;
                uint64_t fpair = (j & 1) ? fp[j >> 1].y : fp[j >> 1].x;
                uint64_t W0 = packf2(ex2f(qd[s0 % 3] * cf[s0]), ex2f(qd[s1 % 3] * cf[s1]));
                uint64_t W1 = packf2(ex2f(qe[s0 % 3] * cf[s0]), ex2f(qe[s1 % 3] * cf[s1]));
                acc2[0][j] = fma2(fpair, W0, acc2[0][j]);
                acc2[1][j] = fma2(fpair, W1, acc2[1][j]);
            }
        }
    }

    // Unpack to 15 scalars per m.
    float acc_s[2][15];
    #pragma unroll
    for (int t = 0; t < 2; t++) {
        #pragma unroll
        for (int j = 0; j < 8; j++) {
            float lo, hi;
            unpackf2(acc2[t][j], lo, hi);
            if (2*j     < 15) acc_s[t][2*j]     = lo;
            if (2*j + 1 < 15) acc_s[t][2*j + 1] = hi;
        }
    }

    // Cross-warp reduction: 16 partials per (m_loc, i), padded rows (RSTRIDE=17).
    __syncthreads();
    float* red = smem;                       // [16][64][17] = 17408 floats <= 20496
    {
        float* d0 = &red[(wid * 64 + lane) * RSTRIDE];
        float* d1 = &red[(wid * 64 + 32 + lane) * RSTRIDE];
        #pragma unroll
        for (int i = 0; i < 15; i++) { d0[i] = acc_s[0][i]; d1[i] = acc_s[1][i]; }
    }
    __syncthreads();

    // 960 outputs per block; 512 threads -> strided loop.
    for (int o = tid; o < M_BLK * 15; o += THREADS) {
        int m_loc = o / 15, i = o - m_loc * 15;
        float s = 0.f;
        #pragma unroll
        for (int w = 0; w < WARPS; w++)
            s += red[(w * 64 + m_loc) * RSTRIDE + i];
        out[((size_t)b * N2_ + m_base) * 15 + o] = s;
    }
}

extern "C" void kernel_launch(void* const* d_in, const int* in_sizes, int n_in,
                              void* d_out, int out_size)
{
    const float* xa   = (const float*)d_in[0];
    const float* feat = (const float*)d_in[1];
    const float* xt   = (const float*)d_in[2];
    const float* lstd = (const float*)d_in[3];
    float* out = (float*)d_out;

    const size_t smem = SMEM_FLOATS * sizeof(float);   // ~80 KB dynamic
    cudaFuncSetAttribute(icgp_kernel, cudaFuncAttributeMaxDynamicSharedMemorySize, (int)smem);

    dim3 grid(N2_ / M_BLK, B_);   // (16, 8) = 128 blocks
    icgp_kernel<<<grid, THREADS, smem>>>(xa, feat, xt, lstd, out);
}

// round 16
// speedup vs baseline: 1.1201x; 1.0135x over previous
#include <cuda_runtime.h>
#include <cstdint>

// ICGP_Convnp: out[b,m,k,c] = sum_n feat[b,n,k,c] * exp(-0.5*((xa[b,n,c]-xt[b,m,c])/std[k,c])^2)
// B=8, N1=N2=1024, D=1, K=5, C=3.
// lane -> 2 m's, warp -> n-chunk (64), k-loop = packed fma.rn.f32x2.
// Software-pipelined main loop: prefetch next n's xa + feature row past the LDS latency.

constexpr int B_  = 8;
constexpr int N1_ = 1024;
constexpr int N2_ = 1024;

constexpr int WARPS    = 16;
constexpr int THREADS  = WARPS * 32;       // 512
constexpr int NCHUNK   = N1_ / WARPS;      // 64 n per warp
constexpr int M_BLK    = 64;               // 2 m per lane
constexpr int FSTRIDE  = 16;               // feature row padded 15 -> 16 floats (64B)
constexpr int XSTRIDE  = 4;
// + one pad feature row so the last prefetch (row 1024) stays in-bounds.
constexpr int SMEM_FLOATS = N1_ * XSTRIDE + (N1_ + 1) * FSTRIDE;  // 20496 floats
constexpr int RSTRIDE  = 17;               // padded reduction row (conflict-free)

__device__ __forceinline__ float ex2f(float x) {
    float y;
    asm("ex2.approx.ftz.f32 %0, %1;" : "=f"(y) : "f"(x));
    return y;
}
__device__ __forceinline__ uint64_t packf2(float lo, float hi) {
    uint64_t r;
    asm("mov.b64 %0, {%1, %2};" : "=l"(r) : "f"(lo), "f"(hi));
    return r;
}
__device__ __forceinline__ uint64_t fma2(uint64_t a, uint64_t b, uint64_t c) {
    uint64_t d;
    asm("fma.rn.f32x2 %0, %1, %2, %3;" : "=l"(d) : "l"(a), "l"(b), "l"(c));
    return d;
}
__device__ __forceinline__ void unpackf2(uint64_t v, float& lo, float& hi) {
    asm("mov.b64 {%0, %1}, %2;" : "=f"(lo), "=f"(hi) : "l"(v));
}

__global__ __launch_bounds__(THREADS, 1)
void icgp_kernel(const float* __restrict__ xa, const float* __restrict__ feat,
                 const float* __restrict__ xt, const float* __restrict__ lstd,
                 float* __restrict__ out)
{
    extern __shared__ float smem[];
    float* s_xa = smem;                      // [N1][4]
    float* s_ft = smem + N1_ * XSTRIDE;      // [N1+1][16], slots 0..14 = (k,c), slot 15 = 0
    __shared__ float s_coef[16];
    __shared__ int   s_uni;

    const int b      = blockIdx.y;
    const int tid    = threadIdx.x;
    const int wid    = tid >> 5;
    const int lane   = tid & 31;
    const int m_base = blockIdx.x * M_BLK;
    const int m0     = m_base + lane;
    const int m1     = m0 + 32;

    // coef[k,c] = -0.5*log2(e) / (exp(log_std)+eps)^2
    if (tid < 15) {
        float s = __expf(lstd[tid]) + 1e-6f;
        s_coef[tid] = -0.72134752044448170f / (s * s);
    }
    if (tid == 15) s_coef[15] = 0.f;
    __syncthreads();
    if (tid == 0) {
        int u = 1;
        #pragma unroll
        for (int i = 1; i < 15; i++)
            u &= (__float_as_int(s_coef[i]) == __float_as_int(s_coef[0]));
        s_uni = u;
    }

    // Stage xa[b] into padded shared.
    const float* xa_b = xa + (size_t)b * N1_ * 3;
    for (int n = tid; n < N1_; n += THREADS) {
        s_xa[n * XSTRIDE + 0] = xa_b[n * 3 + 0];
        s_xa[n * XSTRIDE + 1] = xa_b[n * 3 + 1];
        s_xa[n * XSTRIDE + 2] = xa_b[n * 3 + 2];
        s_xa[n * XSTRIDE + 3] = 0.f;
    }
    // Zero slot 15 of every feature row + the pad row (row N1).
    for (int n = tid; n < N1_; n += THREADS)
        s_ft[n * FSTRIDE + 15] = 0.f;
    if (tid < FSTRIDE) s_ft[N1_ * FSTRIDE + tid] = 0.f;
    // Stage features[b] with float4 loads (3840 float4, 16B-aligned).
    {
        const float4* f4 = reinterpret_cast<const float4*>(feat + (size_t)b * N1_ * 15);
        for (int v = tid; v < N1_ * 15 / 4; v += THREADS) {
            float4 f = f4[v];
            int g = v * 4;
            int n = g / 15, s = g - n * 15;
            s_ft[n * FSTRIDE + s] = f.x;
            if (++s == 15) { s = 0; n++; }
            s_ft[n * FSTRIDE + s] = f.y;
            if (++s == 15) { s = 0; n++; }
            s_ft[n * FSTRIDE + s] = f.z;
            if (++s == 15) { s = 0; n++; }
            s_ft[n * FSTRIDE + s] = f.w;
        }
    }
    __syncthreads();

    // Per-lane target points (2 m's).
    const float* xt_b = xt + (size_t)b * N2_ * 3;
    const float t0r = xt_b[m0 * 3 + 0], t1r = xt_b[m0 * 3 + 1], t2r = xt_b[m0 * 3 + 2];
    const float u0r = xt_b[m1 * 3 + 0], u1r = xt_b[m1 * 3 + 1], u2r = xt_b[m1 * 3 + 2];

    const int n0 = wid * NCHUNK;

    uint64_t acc2[2][8];
    #pragma unroll
    for (int j = 0; j < 8; j++) { acc2[0][j] = 0ull; acc2[1][j] = 0ull; }

    if (s_uni) {
        // w_c = exp2(-((a_c - t_c)*sgm)^2),  sgm = sqrt(-c0)
        const float sgm = sqrtf(-s_coef[0]);
        const float t0 = t0r * sgm, t1 = t1r * sgm, t2 = t2r * sgm;
        const float v0 = u0r * sgm, v1 = u1r * sgm, v2 = u2r * sgm;

        const float4*     xp = reinterpret_cast<const float4*>(&s_xa[n0 * XSTRIDE]);
        const ulonglong2* fp = reinterpret_cast<const ulonglong2*>(&s_ft[n0 * FSTRIDE]);

        // Pipeline prologue: load iteration 0's operands.
        float4 a_c = xp[0];
        ulonglong2 pA = fp[0], pB = fp[1], pC = fp[2], pD = fp[3];

        #pragma unroll 2
        for (int it = 0; it < NCHUNK; it++) {
            // Prefetch next iteration (pad row makes it always in-bounds).
            float4 a_n = xp[it + 1];
            ulonglong2 qA = fp[4*(it+1) + 0], qB = fp[4*(it+1) + 1],
                       qC = fp[4*(it+1) + 2], qD = fp[4*(it+1) + 3];

            float p0 = fmaf(a_c.x, sgm, -t0);
            float p1 = fmaf(a_c.y, sgm, -t1);
            float p2 = fmaf(a_c.z, sgm, -t2);
            float w0 = ex2f(p0 * -p0), w1 = ex2f(p1 * -p1), w2 = ex2f(p2 * -p2);
            float q0 = fmaf(a_c.x, sgm, -v0);
            float q1 = fmaf(a_c.y, sgm, -v1);
            float q2 = fmaf(a_c.z, sgm, -v2);
            float x0 = ex2f(q0 * -q0), x1 = ex2f(q1 * -q1), x2 = ex2f(q2 * -q2);
            // packed weight pattern over 16-slot row: A B C A B C A B
            uint64_t A0 = packf2(w0, w1), B0 = packf2(w2, w0), C0 = packf2(w1, w2);
            uint64_t A1 = packf2(x0, x1), B1 = packf2(x2, x0), C1 = packf2(x1, x2);

            acc2[0][0] = fma2(pA.x, A0, acc2[0][0]);
            acc2[1][0] = fma2(pA.x, A1, acc2[1][0]);
            acc2[0][1] = fma2(pA.y, B0, acc2[0][1]);
            acc2[1][1] = fma2(pA.y, B1, acc2[1][1]);
            acc2[0][2] = fma2(pB.x, C0, acc2[0][2]);
            acc2[1][2] = fma2(pB.x, C1, acc2[1][2]);
            acc2[0][3] = fma2(pB.y, A0, acc2[0][3]);
            acc2[1][3] = fma2(pB.y, A1, acc2[1][3]);
            acc2[0][4] = fma2(pC.x, B0, acc2[0][4]);
            acc2[1][4] = fma2(pC.x, B1, acc2[1][4]);
            acc2[0][5] = fma2(pC.y, C0, acc2[0][5]);
            acc2[1][5] = fma2(pC.y, C1, acc2[1][5]);
            acc2[0][6] = fma2(pD.x, A0, acc2[0][6]);
            acc2[1][6] = fma2(pD.x, A1, acc2[1][6]);
            acc2[0][7] = fma2(pD.y, B0, acc2[0][7]);   // slot15 feature = 0
            acc2[1][7] = fma2(pD.y, B1, acc2[1][7]);

            a_c = a_n; pA = qA; pB = qB; pC = qC; pD = qD;
        }
    } else {
        // General path: per-(k,c) bandwidth; packed accumulation (same epilogue).
        float cf[16];
        #pragma unroll
        for (int i = 0; i < 16; i++) cf[i] = s_coef[i];
        for (int n = n0; n < n0 + NCHUNK; n++) {
            float4 a = *reinterpret_cast<const float4*>(&s_xa[n * XSTRIDE]);
            float qd[3], qe[3];
            qd[0] = (a.x - t0r) * (a.x - t0r);
            qd[1] = (a.y - t1r) * (a.y - t1r);
            qd[2] = (a.z - t2r) * (a.z - t2r);
            qe[0] = (a.x - u0r) * (a.x - u0r);
            qe[1] = (a.y - u1r) * (a.y - u1r);
            qe[2] = (a.z - u2r) * (a.z - u2r);
            const ulonglong2* fp = reinterpret_cast<const ulonglong2*>(&s_ft[n * FSTRIDE]);
            #pragma unroll
            for (int j = 0; j < 8; j++) {
                const int s0 = 2 * j, s1 = 2 * j + 1;
                uint64_t fpair = (j & 1) ? fp[j >> 1].y : fp[j >> 1].x;
                uint64_t W0 = packf2(ex2f(qd[s0 % 3] * cf[s0]), ex2f(qd[s1 % 3] * cf[s1]));
                uint64_t W1 = packf2(ex2f(qe[s0 % 3] * cf[s0]), ex2f(qe[s1 % 3] * cf[s1]));
                acc2[0][j] = fma2(fpair, W0, acc2[0][j]);
                acc2[1][j] = fma2(fpair, W1, acc2[1][j]);
            }
        }
    }

    // Unpack to 15 scalars per m.
    float acc_s[2][15];
    #pragma unroll
    for (int t = 0; t < 2; t++) {
        #pragma unroll
        for (int j = 0; j < 8; j++) {
            float lo, hi;
            unpackf2(acc2[t][j], lo, hi);
            if (2*j     < 15) acc_s[t][2*j]     = lo;
            if (2*j + 1 < 15) acc_s[t][2*j + 1] = hi;
        }
    }

    // Cross-warp reduction: 16 partials per (m_loc, i), padded rows (RSTRIDE=17).
    __syncthreads();
    float* red = smem;                       // [16][64][17] = 17408 floats <= 20496
    {
        float* d0 = &red[(wid * 64 + lane) * RSTRIDE];
        float* d1 = &red[(wid * 64 + 32 + lane) * RSTRIDE];
        #pragma unroll
        for (int i = 0; i < 15; i++) { d0[i] = acc_s[0][i]; d1[i] = acc_s[1][i]; }
    }
    __syncthreads();

    // 960 outputs per block; 512 threads -> strided loop.
    for (int o = tid; o < M_BLK * 15; o += THREADS) {
        int m_loc = o / 15, i = o - m_loc * 15;
        float s = 0.f;
        #pragma unroll
        for (int w = 0; w < WARPS; w++)
            s += red[(w * 64 + m_loc) * RSTRIDE + i];
        out[((size_t)b * N2_ + m_base) * 15 + o] = s;
    }
}

extern "C" void kernel_launch(void* const* d_in, const int* in_sizes, int n_in,
                              void* d_out, int out_size)
{
    const float* xa   = (const float*)d_in[0];
    const float* feat = (const float*)d_in[1];
    const float* xt   = (const float*)d_in[2];
    const float* lstd = (const float*)d_in[3];
    float* out = (float*)d_out;

    const size_t smem = SMEM_FLOATS * sizeof(float);   // ~80 KB dynamic
    cudaFuncSetAttribute(icgp_kernel, cudaFuncAttributeMaxDynamicSharedMemorySize, (int)smem);

    dim3 grid(N2_ / M_BLK, B_);   // (16, 8) = 128 blocks
    icgp_kernel<<<grid, THREADS, smem>>>(xa, feat, xt, lstd, out);
}